// round 15
// baseline (speedup 1.0000x reference)
#include <cuda_runtime.h>
#include <cuda_fp16.h>
#include <cstdint>

// ---------------- problem constants (fixed by reference_code) ----------------
#define N_USERS 100000
#define N_ITEMS 50000
#define N_NODES 150000
#define KPU 32
#define E_UI  (N_USERS * KPU)
#define SELF_BASE (2 * E_UI)
#define D 64
#define OD 256
#define MAXDEG 128
#define TILE_M 128
#define NTILES ((N_NODES + TILE_M - 1) / TILE_M)   // 1172

// padded smem strides (halves) -> conflict-free fragment loads
#define SA_STRIDE 136
#define SW_STRIDE 136
#define SF_STRIDE 68            // float stride for epilogue bounce (aliases sA)
// dynamic smem layout (bytes)
#define SM_A     0
#define SM_W     (128 * SA_STRIDE * 2)                 // 34816
#define SM_BIAS  (SM_W + 64 * SW_STRIDE * 2)           // 52224
#define SM_TOTAL (SM_BIAS + 64 * 4)                    // 52480

// ---------------- device scratch (no allocation allowed) ----------------
__device__ int    g_fill[N_ITEMS];
__device__ int    g_adj2[(size_t)N_ITEMS * MAXDEG];   // padded item->user lists
__device__ __align__(128) __half g_ph[2][(size_t)N_NODES * D];  // fp16 ping-pong

#define H2(u) (*reinterpret_cast<const __half2*>(&(u)))

// ---------------- CSR build ----------------
__global__ void zero_fill_kernel() {
    int i = blockIdx.x * blockDim.x + threadIdx.x;
    if (i < N_ITEMS) g_fill[i] = 0;
}
__global__ void fill2_kernel(const int* __restrict__ cols) {
    int e = blockIdx.x * blockDim.x + threadIdx.x;
    if (e >= E_UI) return;
    int item = cols[e] - N_USERS;
    int pos  = atomicAdd(&g_fill[item], 1);
    if (pos < MAXDEG) g_adj2[item * MAXDEG + pos] = e >> 5;
}

// ---------------- ego copy: out[:,0:64] = concat(ue, ie); fp16 pack buf 0 ----
__global__ void ego_copy_kernel(const float* __restrict__ ue,
                                const float* __restrict__ ie,
                                float* __restrict__ out) {
    int idx = blockIdx.x * blockDim.x + threadIdx.x;
    if (idx >= N_NODES * (D / 4)) return;
    int n  = idx >> 4;
    int c4 = idx & 15;
    float4 v = (n < N_USERS)
        ? reinterpret_cast<const float4*>(ue)[(size_t)n * (D/4) + c4]
        : reinterpret_cast<const float4*>(ie)[(size_t)(n - N_USERS) * (D/4) + c4];
    reinterpret_cast<float4*>(out)[(size_t)n * (OD/4) + c4] = v;
    __half2 h0 = __floats2half2_rn(v.x, v.y);
    __half2 h1 = __floats2half2_rn(v.z, v.w);
    reinterpret_cast<uint2*>(g_ph[0])[(size_t)n * (D/4) + c4] =
        make_uint2(*reinterpret_cast<unsigned*>(&h0), *reinterpret_cast<unsigned*>(&h1));
}

// 4-deep quarter-warp gather: 4 independent LDG.128 (each lane = 16B of a row),
// fp16 tree-sum, fp32 accumulate into 8 per-lane columns.
__device__ __forceinline__ void gather4q(const __half* __restrict__ ph,
                                         int c0, int c1, int c2, int c3,
                                         int ql, float* acc) {
    const uint4 v0 = *reinterpret_cast<const uint4*>(ph + (size_t)c0 * D + ql * 8);
    const uint4 v1 = *reinterpret_cast<const uint4*>(ph + (size_t)c1 * D + ql * 8);
    const uint4 v2 = *reinterpret_cast<const uint4*>(ph + (size_t)c2 * D + ql * 8);
    const uint4 v3 = *reinterpret_cast<const uint4*>(ph + (size_t)c3 * D + ql * 8);
    __half2 s0 = __hadd2(__hadd2(H2(v0.x), H2(v1.x)), __hadd2(H2(v2.x), H2(v3.x)));
    __half2 s1 = __hadd2(__hadd2(H2(v0.y), H2(v1.y)), __hadd2(H2(v2.y), H2(v3.y)));
    __half2 s2 = __hadd2(__hadd2(H2(v0.z), H2(v1.z)), __hadd2(H2(v2.z), H2(v3.z)));
    __half2 s3 = __hadd2(__hadd2(H2(v0.w), H2(v1.w)), __hadd2(H2(v2.w), H2(v3.w)));
    float2 f;
    f = __half22float2(s0); acc[0] += f.x; acc[1] += f.y;
    f = __half22float2(s1); acc[2] += f.x; acc[3] += f.y;
    f = __half22float2(s2); acc[4] += f.x; acc[5] += f.y;
    f = __half22float2(s3); acc[6] += f.x; acc[7] += f.y;
}

// warp HMMA: D[16,8] += A[16,16] * B[16,8]^T (f16 in, f32 acc)
__device__ __forceinline__ void mma16816(float* c, uint32_t a0, uint32_t a1,
                                         uint32_t a2, uint32_t a3,
                                         uint32_t b0, uint32_t b1) {
    asm volatile(
        "mma.sync.aligned.m16n8k16.row.col.f32.f16.f16.f32 "
        "{%0,%1,%2,%3}, {%4,%5,%6,%7}, {%8,%9}, {%0,%1,%2,%3};"
        : "+f"(c[0]), "+f"(c[1]), "+f"(c[2]), "+f"(c[3])
        : "r"(a0), "r"(a1), "r"(a2), "r"(a3), "r"(b0), "r"(b1));
}

// ---------------- fused layer: fp16 gather -> HMMA GEMM -> epilogue ----------
__global__ void __launch_bounds__(256, 4)
fused_layer_mma(const int* __restrict__ cols,
                const float* __restrict__ vals,
                float* __restrict__ outc,           // fp32, stride OD
                const float* __restrict__ Ws, const float* __restrict__ bs,
                const float* __restrict__ Wp, const float* __restrict__ bp,
                int srcbuf, int ntiles) {
    extern __shared__ char smem[];
    __half* sA    = reinterpret_cast<__half*>(smem + SM_A);
    float*  sF    = reinterpret_cast<float*>(smem + SM_A);   // epilogue bounce
    __half* sW    = reinterpret_cast<__half*>(smem + SM_W);
    float*  sbias = reinterpret_cast<float*>(smem + SM_BIAS);

    const __half* ph  = g_ph[srcbuf];
    __half*       phd = g_ph[srcbuf ^ 1];

    int tx = threadIdx.x;

    // stage weights transposed: sW[n][k] = (k<64 ? Ws[k][n] : Wp[k-64][n])
    for (int idx = tx; idx < 64 * 128; idx += 256) {
        int n = idx >> 7;
        int k = idx & 127;
        float w = (k < 64) ? Ws[k * 64 + n] : Wp[(k - 64) * 64 + n];
        sW[n * SW_STRIDE + k] = __float2half_rn(w);
    }
    if (tx < 64) sbias[tx] = bs[tx] + bp[tx];

    int q   = tx >> 3;                 // quarter-warp id 0..31 (gather phase)
    int ql  = tx & 7;                  // lane within quad
    unsigned qmask = 0xFFu << (tx & 24);
    int h  = tx >> 4;                  // half-warp id (writeout phase)
    int hl = tx & 15;
    int w    = tx >> 5;                // warp id (mma phase)
    int lane = tx & 31;
    int g    = lane >> 2;              // fragment row group
    int t    = lane & 3;               // fragment thread-in-group
    __syncthreads();

    for (int tile = blockIdx.x; tile < ntiles; tile += gridDim.x) {
        int tb = tile * TILE_M;

        // ---- Phase A: each quad gathers+stages 4 full rows (LDG.128) ----
        #pragma unroll
        for (int i = 0; i < 4; i++) {
            int r = q * 4 + i;
            int n = tb + r;
            uint4* dS = reinterpret_cast<uint4*>(sA + r * SA_STRIDE + ql * 8);
            uint4* dP = reinterpret_cast<uint4*>(sA + r * SA_STRIDE + 64 + ql * 8);
            if (n >= N_NODES) {
                *dS = make_uint4(0u, 0u, 0u, 0u);
                *dP = make_uint4(0u, 0u, 0u, 0u);
                continue;
            }
            // self row: lane owns 8 half-columns
            uint4 us = *reinterpret_cast<const uint4*>(ph + (size_t)n * D + ql * 8);
            float pself[8], acc[8];
            {
                float2 f;
                f = __half22float2(H2(us.x)); pself[0] = f.x; pself[1] = f.y;
                f = __half22float2(H2(us.y)); pself[2] = f.x; pself[3] = f.y;
                f = __half22float2(H2(us.z)); pself[4] = f.x; pself[5] = f.y;
                f = __half22float2(H2(us.w)); pself[6] = f.x; pself[7] = f.y;
                #pragma unroll
                for (int c = 0; c < 8; c++) acc[c] = pself[c];
            }
            if (n < N_USERS) {
                // lane ql holds neighbors 4ql..4ql+3 (order irrelevant: sum)
                int4 ci = reinterpret_cast<const int4*>(cols + n * KPU)[ql];
                #pragma unroll
                for (int l = 0; l < 8; l++) {
                    int c0 = __shfl_sync(qmask, ci.x, l, 8);
                    int c1 = __shfl_sync(qmask, ci.y, l, 8);
                    int c2 = __shfl_sync(qmask, ci.z, l, 8);
                    int c3 = __shfl_sync(qmask, ci.w, l, 8);
                    gather4q(ph, c0, c1, c2, c3, ql, acc);
                }
            } else {
                int it  = n - N_USERS;
                int cnt = g_fill[it]; if (cnt > MAXDEG) cnt = MAXDEG;
                const int* adj = g_adj2 + (size_t)it * MAXDEG;
                int p = 0;
                for (; p + 8 <= cnt; p += 8) {
                    int myu = adj[p + ql];
                    int c0 = __shfl_sync(qmask, myu, 0, 8);
                    int c1 = __shfl_sync(qmask, myu, 1, 8);
                    int c2 = __shfl_sync(qmask, myu, 2, 8);
                    int c3 = __shfl_sync(qmask, myu, 3, 8);
                    gather4q(ph, c0, c1, c2, c3, ql, acc);
                    c0 = __shfl_sync(qmask, myu, 4, 8);
                    c1 = __shfl_sync(qmask, myu, 5, 8);
                    c2 = __shfl_sync(qmask, myu, 6, 8);
                    c3 = __shfl_sync(qmask, myu, 7, 8);
                    gather4q(ph, c0, c1, c2, c3, ql, acc);
                }
                int rem = cnt - p;
                if (rem > 0) {
                    int myu = (ql < rem) ? adj[p + ql] : 0;
                    for (int j = 0; j < rem; j++) {
                        int uu = __shfl_sync(qmask, myu, j, 8);
                        uint4 u = *reinterpret_cast<const uint4*>(ph + (size_t)uu * D + ql * 8);
                        float2 f;
                        f = __half22float2(H2(u.x)); acc[0] += f.x; acc[1] += f.y;
                        f = __half22float2(H2(u.y)); acc[2] += f.x; acc[3] += f.y;
                        f = __half22float2(H2(u.z)); acc[4] += f.x; acc[5] += f.y;
                        f = __half22float2(H2(u.w)); acc[6] += f.x; acc[7] += f.y;
                    }
                }
            }
            float sv = vals[SELF_BASE + n];   // 1/deg[n]
            __half2 sh[4], phh[4];
            #pragma unroll
            for (int c = 0; c < 4; c++) {
                float s0 = acc[c*2+0] * sv;
                float s1 = acc[c*2+1] * sv;
                sh[c]  = __floats2half2_rn(s0, s1);
                phh[c] = __floats2half2_rn(s0 * pself[c*2+0], s1 * pself[c*2+1]);
            }
            *dS = make_uint4(*reinterpret_cast<unsigned*>(&sh[0]),
                             *reinterpret_cast<unsigned*>(&sh[1]),
                             *reinterpret_cast<unsigned*>(&sh[2]),
                             *reinterpret_cast<unsigned*>(&sh[3]));
            *dP = make_uint4(*reinterpret_cast<unsigned*>(&phh[0]),
                             *reinterpret_cast<unsigned*>(&phh[1]),
                             *reinterpret_cast<unsigned*>(&phh[2]),
                             *reinterpret_cast<unsigned*>(&phh[3]));
        }
        __syncthreads();

        // ---- Phase B: warp stripe GEMM, rows [16w, 16w+16), via HMMA ----
        float acc[8][4];
        #pragma unroll
        for (int nt = 0; nt < 8; nt++) {
            acc[nt][0] = 0.f; acc[nt][1] = 0.f; acc[nt][2] = 0.f; acc[nt][3] = 0.f;
        }
        #pragma unroll
        for (int ks = 0; ks < 8; ks++) {
            const __half* pa = sA + (w * 16 + g) * SA_STRIDE + ks * 16 + t * 2;
            uint32_t a0 = *reinterpret_cast<const uint32_t*>(pa);
            uint32_t a1 = *reinterpret_cast<const uint32_t*>(pa + 8 * SA_STRIDE);
            uint32_t a2 = *reinterpret_cast<const uint32_t*>(pa + 8);
            uint32_t a3 = *reinterpret_cast<const uint32_t*>(pa + 8 * SA_STRIDE + 8);
            #pragma unroll
            for (int nt = 0; nt < 8; nt++) {
                const __half* pb = sW + (nt * 8 + g) * SW_STRIDE + ks * 16 + t * 2;
                uint32_t b0 = *reinterpret_cast<const uint32_t*>(pb);
                uint32_t b1 = *reinterpret_cast<const uint32_t*>(pb + 8);
                mma16816(acc[nt], a0, a1, a2, a3, b0, b1);
            }
        }

        // ---- epilogue: bias + lrelu + L2 norm, bounce through smem ----
        {
            int lr0 = w * 16 + g;
            int lr1 = lr0 + 8;
            float sq0 = 0.f, sq1 = 0.f;
            #pragma unroll
            for (int nt = 0; nt < 8; nt++) {
                float b0v = sbias[nt * 8 + t * 2];
                float b1v = sbias[nt * 8 + t * 2 + 1];
                float v;
                v = acc[nt][0] + b0v; v = (v >= 0.f) ? v : 0.2f * v; acc[nt][0] = v; sq0 += v * v;
                v = acc[nt][1] + b1v; v = (v >= 0.f) ? v : 0.2f * v; acc[nt][1] = v; sq0 += v * v;
                v = acc[nt][2] + b0v; v = (v >= 0.f) ? v : 0.2f * v; acc[nt][2] = v; sq1 += v * v;
                v = acc[nt][3] + b1v; v = (v >= 0.f) ? v : 0.2f * v; acc[nt][3] = v; sq1 += v * v;
            }
            sq0 += __shfl_xor_sync(0xffffffffu, sq0, 1);
            sq0 += __shfl_xor_sync(0xffffffffu, sq0, 2);
            sq1 += __shfl_xor_sync(0xffffffffu, sq1, 1);
            sq1 += __shfl_xor_sync(0xffffffffu, sq1, 2);
            float inv0 = 1.0f / fmaxf(sqrtf(sq0), 1e-12f);
            float inv1 = 1.0f / fmaxf(sqrtf(sq1), 1e-12f);
            #pragma unroll
            for (int nt = 0; nt < 8; nt++) {
                *reinterpret_cast<float2*>(sF + lr0 * SF_STRIDE + nt * 8 + t * 2) =
                    make_float2(acc[nt][0] * inv0, acc[nt][1] * inv0);
                *reinterpret_cast<float2*>(sF + lr1 * SF_STRIDE + nt * 8 + t * 2) =
                    make_float2(acc[nt][2] * inv1, acc[nt][3] * inv1);
            }
        }
        __syncthreads();

        // ---- coalesced writeout: half-warp h writes rows h*8..h*8+7 ----
        #pragma unroll 2
        for (int i = 0; i < 8; i++) {
            int r = h * 8 + i;
            int n = tb + r;
            if (n < N_NODES) {
                float4 v = *reinterpret_cast<const float4*>(sF + r * SF_STRIDE + hl * 4);
                reinterpret_cast<float4*>(outc + (size_t)n * OD)[hl] = v;
                __half2 h0 = __floats2half2_rn(v.x, v.y);
                __half2 h1 = __floats2half2_rn(v.z, v.w);
                reinterpret_cast<uint2*>(phd + (size_t)n * D)[hl] =
                    make_uint2(*reinterpret_cast<unsigned*>(&h0),
                               *reinterpret_cast<unsigned*>(&h1));
            }
        }
        __syncthreads();   // sF/sA reused next tile
    }
}

// ---------------- launch ----------------
extern "C" void kernel_launch(void* const* d_in, const int* in_sizes, int n_in,
                              void* d_out, int out_size) {
    (void)in_sizes; (void)n_in; (void)out_size;
    const int*   cols = (const int*)d_in[1];
    const float* vals = (const float*)d_in[2];
    const float* ue   = (const float*)d_in[3];
    const float* ie   = (const float*)d_in[4];
    float* out = (float*)d_out;

    static int smem_set = 0;
    if (!smem_set) {
        cudaFuncSetAttribute(fused_layer_mma,
                             cudaFuncAttributeMaxDynamicSharedMemorySize, SM_TOTAL);
        smem_set = 1;
    }

    zero_fill_kernel<<<(N_ITEMS + 255) / 256, 256>>>();
    fill2_kernel<<<(E_UI + 255) / 256, 256>>>(cols);
    ego_copy_kernel<<<(N_NODES * (D/4) + 255) / 256, 256>>>(ue, ie, out);

    int nblk = 148 * 4;   // grid-stride, one wave at 4 CTAs/SM
    for (int k = 0; k < 3; k++) {
        float* outc = out + (size_t)64 * (k + 1);
        const float* Ws = (const float*)d_in[5 + 4 * k + 0];
        const float* bs = (const float*)d_in[5 + 4 * k + 1];
        const float* Wp = (const float*)d_in[5 + 4 * k + 2];
        const float* bp = (const float*)d_in[5 + 4 * k + 3];
        fused_layer_mma<<<nblk, 256, SM_TOTAL>>>(cols, vals, outc,
                                                 Ws, bs, Wp, bp, k & 1, NTILES);
    }
}

// round 16
// speedup vs baseline: 1.0317x; 1.0317x over previous
#include <cuda_runtime.h>
#include <cuda_fp16.h>
#include <cstdint>

// ---------------- problem constants (fixed by reference_code) ----------------
#define N_USERS 100000
#define N_ITEMS 50000
#define N_NODES 150000
#define KPU 32
#define E_UI  (N_USERS * KPU)
#define SELF_BASE (2 * E_UI)
#define D 64
#define OD 256
#define MAXDEG 128
#define TILE_M 128
#define NTILES ((N_NODES + TILE_M - 1) / TILE_M)   // 1172

// padded smem strides (halves) -> conflict-free fragment loads
#define SA_STRIDE 136
#define SW_STRIDE 136
#define SF_STRIDE 68            // float stride for epilogue bounce (aliases sA)
// dynamic smem layout (bytes)
#define SM_A     0
#define SM_W     (128 * SA_STRIDE * 2)                 // 34816
#define SM_BIAS  (SM_W + 64 * SW_STRIDE * 2)           // 52224
#define SM_TOTAL (SM_BIAS + 64 * 4)                    // 52480

// ---------------- device scratch (no allocation allowed) ----------------
__device__ int    g_fill[N_ITEMS];
__device__ int    g_adj2[(size_t)N_ITEMS * MAXDEG];   // padded item->user lists
__device__ __align__(128) __half g_ph[2][(size_t)N_NODES * D];  // fp16 ping-pong

#define H2(u) (*reinterpret_cast<const __half2*>(&(u)))

// ---------------- CSR build ----------------
__global__ void zero_fill_kernel() {
    int i = blockIdx.x * blockDim.x + threadIdx.x;
    if (i < N_ITEMS) g_fill[i] = 0;
}
__global__ void fill2_kernel(const int* __restrict__ cols) {
    int e = blockIdx.x * blockDim.x + threadIdx.x;
    if (e >= E_UI) return;
    int item = cols[e] - N_USERS;
    int pos  = atomicAdd(&g_fill[item], 1);
    if (pos < MAXDEG) g_adj2[item * MAXDEG + pos] = e >> 5;
}

// ---------------- ego copy: out[:,0:64] = concat(ue, ie); fp16 pack buf 0 ----
__global__ void ego_copy_kernel(const float* __restrict__ ue,
                                const float* __restrict__ ie,
                                float* __restrict__ out) {
    int idx = blockIdx.x * blockDim.x + threadIdx.x;
    if (idx >= N_NODES * (D / 4)) return;
    int n  = idx >> 4;
    int c4 = idx & 15;
    float4 v = (n < N_USERS)
        ? reinterpret_cast<const float4*>(ue)[(size_t)n * (D/4) + c4]
        : reinterpret_cast<const float4*>(ie)[(size_t)(n - N_USERS) * (D/4) + c4];
    reinterpret_cast<float4*>(out)[(size_t)n * (OD/4) + c4] = v;
    __half2 h0 = __floats2half2_rn(v.x, v.y);
    __half2 h1 = __floats2half2_rn(v.z, v.w);
    reinterpret_cast<uint2*>(g_ph[0])[(size_t)n * (D/4) + c4] =
        make_uint2(*reinterpret_cast<unsigned*>(&h0), *reinterpret_cast<unsigned*>(&h1));
}

// 8-deep fp16 gather batch: 8 independent LDG.64.CG (L2-only, no L1 alloc),
// fp16 tree-sum, fp32 hand-off.
__device__ __forceinline__ void gather8h(const __half* __restrict__ ph,
                                         unsigned hmask, int src, int base,
                                         int hl, float4& acc) {
    uint2 v[8];
    #pragma unroll
    for (int j = 0; j < 8; j++) {
        int c = __shfl_sync(hmask, src, base + j, 16);
        v[j] = __ldcg(reinterpret_cast<const uint2*>(ph + (size_t)c * D) + hl);
    }
    __half2 l01 = __hadd2(H2(v[0].x), H2(v[1].x));
    __half2 l23 = __hadd2(H2(v[2].x), H2(v[3].x));
    __half2 l45 = __hadd2(H2(v[4].x), H2(v[5].x));
    __half2 l67 = __hadd2(H2(v[6].x), H2(v[7].x));
    __half2 h01 = __hadd2(H2(v[0].y), H2(v[1].y));
    __half2 h23 = __hadd2(H2(v[2].y), H2(v[3].y));
    __half2 h45 = __hadd2(H2(v[4].y), H2(v[5].y));
    __half2 h67 = __hadd2(H2(v[6].y), H2(v[7].y));
    __half2 lo = __hadd2(__hadd2(l01, l23), __hadd2(l45, l67));
    __half2 hi = __hadd2(__hadd2(h01, h23), __hadd2(h45, h67));
    float2 fl = __half22float2(lo);
    float2 fh = __half22float2(hi);
    acc.x += fl.x; acc.y += fl.y; acc.z += fh.x; acc.w += fh.y;
}

// warp HMMA: D[16,8] += A[16,16] * B[16,8]^T (f16 in, f32 acc)
__device__ __forceinline__ void mma16816(float* c, uint32_t a0, uint32_t a1,
                                         uint32_t a2, uint32_t a3,
                                         uint32_t b0, uint32_t b1) {
    asm volatile(
        "mma.sync.aligned.m16n8k16.row.col.f32.f16.f16.f32 "
        "{%0,%1,%2,%3}, {%4,%5,%6,%7}, {%8,%9}, {%0,%1,%2,%3};"
        : "+f"(c[0]), "+f"(c[1]), "+f"(c[2]), "+f"(c[3])
        : "r"(a0), "r"(a1), "r"(a2), "r"(a3), "r"(b0), "r"(b1));
}

// ---------------- fused layer: fp16 gather -> HMMA GEMM -> epilogue ----------
__global__ void __launch_bounds__(256, 4)
fused_layer_mma(const int* __restrict__ cols,
                const float* __restrict__ vals,
                float* __restrict__ outc,           // fp32, stride OD
                const float* __restrict__ Ws, const float* __restrict__ bs,
                const float* __restrict__ Wp, const float* __restrict__ bp,
                int srcbuf, int ntiles) {
    extern __shared__ char smem[];
    __half* sA    = reinterpret_cast<__half*>(smem + SM_A);
    float*  sF    = reinterpret_cast<float*>(smem + SM_A);   // epilogue bounce
    __half* sW    = reinterpret_cast<__half*>(smem + SM_W);
    float*  sbias = reinterpret_cast<float*>(smem + SM_BIAS);

    const __half* ph  = g_ph[srcbuf];
    __half*       phd = g_ph[srcbuf ^ 1];

    int tx = threadIdx.x;

    // stage weights transposed: sW[n][k] = (k<64 ? Ws[k][n] : Wp[k-64][n])
    for (int idx = tx; idx < 64 * 128; idx += 256) {
        int n = idx >> 7;
        int k = idx & 127;
        float w = (k < 64) ? Ws[k * 64 + n] : Wp[(k - 64) * 64 + n];
        sW[n * SW_STRIDE + k] = __float2half_rn(w);
    }
    if (tx < 64) sbias[tx] = bs[tx] + bp[tx];

    int h  = tx >> 4;          // half-warp id (gather/writeout phases)
    int hl = tx & 15;
    unsigned hmask = 0xFFFFu << (tx & 16);
    int w    = tx >> 5;        // warp id (mma phase)
    int lane = tx & 31;
    int g    = lane >> 2;      // fragment row group
    int t    = lane & 3;       // fragment thread-in-group
    __syncthreads();

    for (int tile = blockIdx.x; tile < ntiles; tile += gridDim.x) {
        int tb = tile * TILE_M;

        // ---- Phase A: gather 8 rows per half-warp (all-fp16 src), stage ----
        #pragma unroll 2
        for (int i = 0; i < 8; i++) {
            int r = h * 8 + i;
            int n = tb + r;
            uint2* dS = reinterpret_cast<uint2*>(sA + r * SA_STRIDE + hl * 4);
            uint2* dP = reinterpret_cast<uint2*>(sA + r * SA_STRIDE + 64 + hl * 4);
            if (n >= N_NODES) {
                *dS = make_uint2(0u, 0u);
                *dP = make_uint2(0u, 0u);
                continue;
            }
            uint2 us = __ldcg(reinterpret_cast<const uint2*>(ph + (size_t)n * D) + hl);
            float2 sa = __half22float2(H2(us.x));
            float2 sb = __half22float2(H2(us.y));
            float4 pself = make_float4(sa.x, sa.y, sb.x, sb.y);
            float4 acc = pself;
            if (n < N_USERS) {
                const int* cu = cols + n * KPU;
                int c_lo = cu[hl];
                int c_hi = cu[16 + hl];
                gather8h(ph, hmask, c_lo, 0, hl, acc);
                gather8h(ph, hmask, c_lo, 8, hl, acc);
                gather8h(ph, hmask, c_hi, 0, hl, acc);
                gather8h(ph, hmask, c_hi, 8, hl, acc);
            } else {
                int it  = n - N_USERS;
                int cnt = g_fill[it]; if (cnt > MAXDEG) cnt = MAXDEG;
                const int* adj = g_adj2 + (size_t)it * MAXDEG;
                int p = 0;
                for (; p + 16 <= cnt; p += 16) {
                    int myu = adj[p + hl];
                    gather8h(ph, hmask, myu, 0, hl, acc);
                    gather8h(ph, hmask, myu, 8, hl, acc);
                }
                int rem = cnt - p;
                if (rem > 0) {
                    int myu = (hl < rem) ? adj[p + hl] : 0;
                    for (int j = 0; j < rem; j++) {
                        int uu = __shfl_sync(hmask, myu, j, 16);
                        uint2 u = __ldcg(reinterpret_cast<const uint2*>(ph + (size_t)uu * D) + hl);
                        float2 a = __half22float2(H2(u.x));
                        float2 b = __half22float2(H2(u.y));
                        acc.x += a.x; acc.y += a.y; acc.z += b.x; acc.w += b.y;
                    }
                }
            }
            float sv = vals[SELF_BASE + n];   // 1/deg[n]
            float4 sd = make_float4(acc.x*sv, acc.y*sv, acc.z*sv, acc.w*sv);
            float4 pp = make_float4(sd.x*pself.x, sd.y*pself.y, sd.z*pself.z, sd.w*pself.w);
            __half2 s0 = __floats2half2_rn(sd.x, sd.y);
            __half2 s1 = __floats2half2_rn(sd.z, sd.w);
            __half2 p0 = __floats2half2_rn(pp.x, pp.y);
            __half2 p1 = __floats2half2_rn(pp.z, pp.w);
            *dS = make_uint2(*reinterpret_cast<unsigned*>(&s0),
                             *reinterpret_cast<unsigned*>(&s1));
            *dP = make_uint2(*reinterpret_cast<unsigned*>(&p0),
                             *reinterpret_cast<unsigned*>(&p1));
        }
        __syncthreads();

        // ---- Phase B: warp stripe GEMM, rows [16w, 16w+16), via HMMA ----
        float acc[8][4];
        #pragma unroll
        for (int nt = 0; nt < 8; nt++) {
            acc[nt][0] = 0.f; acc[nt][1] = 0.f; acc[nt][2] = 0.f; acc[nt][3] = 0.f;
        }
        #pragma unroll
        for (int ks = 0; ks < 8; ks++) {
            const __half* pa = sA + (w * 16 + g) * SA_STRIDE + ks * 16 + t * 2;
            uint32_t a0 = *reinterpret_cast<const uint32_t*>(pa);
            uint32_t a1 = *reinterpret_cast<const uint32_t*>(pa + 8 * SA_STRIDE);
            uint32_t a2 = *reinterpret_cast<const uint32_t*>(pa + 8);
            uint32_t a3 = *reinterpret_cast<const uint32_t*>(pa + 8 * SA_STRIDE + 8);
            #pragma unroll
            for (int nt = 0; nt < 8; nt++) {
                const __half* pb = sW + (nt * 8 + g) * SW_STRIDE + ks * 16 + t * 2;
                uint32_t b0 = *reinterpret_cast<const uint32_t*>(pb);
                uint32_t b1 = *reinterpret_cast<const uint32_t*>(pb + 8);
                mma16816(acc[nt], a0, a1, a2, a3, b0, b1);
            }
        }

        // ---- epilogue: bias + lrelu + L2 norm, bounce through smem ----
        {
            int lr0 = w * 16 + g;
            int lr1 = lr0 + 8;
            float sq0 = 0.f, sq1 = 0.f;
            #pragma unroll
            for (int nt = 0; nt < 8; nt++) {
                float b0v = sbias[nt * 8 + t * 2];
                float b1v = sbias[nt * 8 + t * 2 + 1];
                float v;
                v = acc[nt][0] + b0v; v = (v >= 0.f) ? v : 0.2f * v; acc[nt][0] = v; sq0 += v * v;
                v = acc[nt][1] + b1v; v = (v >= 0.f) ? v : 0.2f * v; acc[nt][1] = v; sq0 += v * v;
                v = acc[nt][2] + b0v; v = (v >= 0.f) ? v : 0.2f * v; acc[nt][2] = v; sq1 += v * v;
                v = acc[nt][3] + b1v; v = (v >= 0.f) ? v : 0.2f * v; acc[nt][3] = v; sq1 += v * v;
            }
            sq0 += __shfl_xor_sync(0xffffffffu, sq0, 1);
            sq0 += __shfl_xor_sync(0xffffffffu, sq0, 2);
            sq1 += __shfl_xor_sync(0xffffffffu, sq1, 1);
            sq1 += __shfl_xor_sync(0xffffffffu, sq1, 2);
            float inv0 = 1.0f / fmaxf(sqrtf(sq0), 1e-12f);
            float inv1 = 1.0f / fmaxf(sqrtf(sq1), 1e-12f);
            #pragma unroll
            for (int nt = 0; nt < 8; nt++) {
                *reinterpret_cast<float2*>(sF + lr0 * SF_STRIDE + nt * 8 + t * 2) =
                    make_float2(acc[nt][0] * inv0, acc[nt][1] * inv0);
                *reinterpret_cast<float2*>(sF + lr1 * SF_STRIDE + nt * 8 + t * 2) =
                    make_float2(acc[nt][2] * inv1, acc[nt][3] * inv1);
            }
        }
        __syncthreads();

        // ---- coalesced writeout: half-warp h writes rows h*8..h*8+7 ----
        #pragma unroll 2
        for (int i = 0; i < 8; i++) {
            int r = h * 8 + i;
            int n = tb + r;
            if (n < N_NODES) {
                float4 v = *reinterpret_cast<const float4*>(sF + r * SF_STRIDE + hl * 4);
                reinterpret_cast<float4*>(outc + (size_t)n * OD)[hl] = v;
                __half2 h0 = __floats2half2_rn(v.x, v.y);
                __half2 h1 = __floats2half2_rn(v.z, v.w);
                reinterpret_cast<uint2*>(phd + (size_t)n * D)[hl] =
                    make_uint2(*reinterpret_cast<unsigned*>(&h0),
                               *reinterpret_cast<unsigned*>(&h1));
            }
        }
        __syncthreads();   // sF/sA reused next tile
    }
}

// ---------------- launch ----------------
extern "C" void kernel_launch(void* const* d_in, const int* in_sizes, int n_in,
                              void* d_out, int out_size) {
    (void)in_sizes; (void)n_in; (void)out_size;
    const int*   cols = (const int*)d_in[1];
    const float* vals = (const float*)d_in[2];
    const float* ue   = (const float*)d_in[3];
    const float* ie   = (const float*)d_in[4];
    float* out = (float*)d_out;

    static int smem_set = 0;
    if (!smem_set) {
        cudaFuncSetAttribute(fused_layer_mma,
                             cudaFuncAttributeMaxDynamicSharedMemorySize, SM_TOTAL);
        smem_set = 1;
    }

    zero_fill_kernel<<<(N_ITEMS + 255) / 256, 256>>>();
    fill2_kernel<<<(E_UI + 255) / 256, 256>>>(cols);
    ego_copy_kernel<<<(N_NODES * (D/4) + 255) / 256, 256>>>(ue, ie, out);

    int nblk = 148 * 4;   // grid-stride, one wave at 4 CTAs/SM
    for (int k = 0; k < 3; k++) {
        float* outc = out + (size_t)64 * (k + 1);
        const float* Ws = (const float*)d_in[5 + 4 * k + 0];
        const float* bs = (const float*)d_in[5 + 4 * k + 1];
        const float* Wp = (const float*)d_in[5 + 4 * k + 2];
        const float* bp = (const float*)d_in[5 + 4 * k + 3];
        fused_layer_mma<<<nblk, 256, SM_TOTAL>>>(cols, vals, outc,
                                                 Ws, bs, Wp, bp, k & 1, NTILES);
    }
}

// round 17
// speedup vs baseline: 1.0702x; 1.0374x over previous
#include <cuda_runtime.h>
#include <cuda_fp16.h>
#include <cstdint>

// ---------------- problem constants (fixed by reference_code) ----------------
#define N_USERS 100000
#define N_ITEMS 50000
#define N_NODES 150000
#define KPU 32
#define E_UI  (N_USERS * KPU)
#define SELF_BASE (2 * E_UI)
#define D 64
#define OD 256
#define MAXDEG 128
#define TILE_M 128
#define NTILES ((N_NODES + TILE_M - 1) / TILE_M)   // 1172

// padded smem strides (halves) -> conflict-free fragment loads
#define SA_STRIDE 136
#define SW_STRIDE 136
#define SF_STRIDE 68            // float stride for epilogue bounce (aliases sA)
// dynamic smem layout (bytes)
#define SM_A     0
#define SM_W     (128 * SA_STRIDE * 2)                 // 34816
#define SM_BIAS  (SM_W + 64 * SW_STRIDE * 2)           // 52224
#define SM_TOTAL (SM_BIAS + 64 * 4)                    // 52480

// ---------------- device scratch (no allocation allowed) ----------------
__device__ int    g_fill[N_ITEMS];
__device__ int    g_adj2[(size_t)N_ITEMS * MAXDEG];   // padded item->user lists
__device__ __align__(128) __half g_ph[2][(size_t)N_NODES * D];  // fp16 ping-pong

#define H2(u) (*reinterpret_cast<const __half2*>(&(u)))

// ---------------- init: zero fill counters + ego copy + fp16 pack (1 launch) -
__global__ void init_kernel(const float* __restrict__ ue,
                            const float* __restrict__ ie,
                            float* __restrict__ out) {
    int idx = blockIdx.x * blockDim.x + threadIdx.x;
    if (idx < N_ITEMS) g_fill[idx] = 0;
    if (idx >= N_NODES * (D / 4)) return;
    int n  = idx >> 4;
    int c4 = idx & 15;
    float4 v = (n < N_USERS)
        ? reinterpret_cast<const float4*>(ue)[(size_t)n * (D/4) + c4]
        : reinterpret_cast<const float4*>(ie)[(size_t)(n - N_USERS) * (D/4) + c4];
    reinterpret_cast<float4*>(out)[(size_t)n * (OD/4) + c4] = v;
    __half2 h0 = __floats2half2_rn(v.x, v.y);
    __half2 h1 = __floats2half2_rn(v.z, v.w);
    reinterpret_cast<uint2*>(g_ph[0])[(size_t)n * (D/4) + c4] =
        make_uint2(*reinterpret_cast<unsigned*>(&h0), *reinterpret_cast<unsigned*>(&h1));
}

__global__ void fill2_kernel(const int* __restrict__ cols) {
    int e = blockIdx.x * blockDim.x + threadIdx.x;
    if (e >= E_UI) return;
    int item = cols[e] - N_USERS;
    int pos  = atomicAdd(&g_fill[item], 1);
    if (pos < MAXDEG) g_adj2[item * MAXDEG + pos] = e >> 5;
}

// 8-deep fp16 gather batch: 8 independent LDG.64.CG, fp16 tree-sum, fp32 hand-off.
__device__ __forceinline__ void gather8h(const __half* __restrict__ ph,
                                         unsigned hmask, int src, int base,
                                         int hl, float4& acc) {
    uint2 v[8];
    #pragma unroll
    for (int j = 0; j < 8; j++) {
        int c = __shfl_sync(hmask, src, base + j, 16);
        v[j] = __ldcg(reinterpret_cast<const uint2*>(ph + (size_t)c * D) + hl);
    }
    __half2 l01 = __hadd2(H2(v[0].x), H2(v[1].x));
    __half2 l23 = __hadd2(H2(v[2].x), H2(v[3].x));
    __half2 l45 = __hadd2(H2(v[4].x), H2(v[5].x));
    __half2 l67 = __hadd2(H2(v[6].x), H2(v[7].x));
    __half2 h01 = __hadd2(H2(v[0].y), H2(v[1].y));
    __half2 h23 = __hadd2(H2(v[2].y), H2(v[3].y));
    __half2 h45 = __hadd2(H2(v[4].y), H2(v[5].y));
    __half2 h67 = __hadd2(H2(v[6].y), H2(v[7].y));
    __half2 lo = __hadd2(__hadd2(l01, l23), __hadd2(l45, l67));
    __half2 hi = __hadd2(__hadd2(h01, h23), __hadd2(h45, h67));
    float2 fl = __half22float2(lo);
    float2 fh = __half22float2(hi);
    acc.x += fl.x; acc.y += fl.y; acc.z += fh.x; acc.w += fh.y;
}

// warp HMMA: D[16,8] += A[16,16] * B[16,8]^T (f16 in, f32 acc)
__device__ __forceinline__ void mma16816(float* c, uint32_t a0, uint32_t a1,
                                         uint32_t a2, uint32_t a3,
                                         uint32_t b0, uint32_t b1) {
    asm volatile(
        "mma.sync.aligned.m16n8k16.row.col.f32.f16.f16.f32 "
        "{%0,%1,%2,%3}, {%4,%5,%6,%7}, {%8,%9}, {%0,%1,%2,%3};"
        : "+f"(c[0]), "+f"(c[1]), "+f"(c[2]), "+f"(c[3])
        : "r"(a0), "r"(a1), "r"(a2), "r"(a3), "r"(b0), "r"(b1));
}

// ---------------- fused layer: fp16 gather -> HMMA GEMM -> epilogue ----------
__global__ void __launch_bounds__(256, 4)
fused_layer_mma(const int* __restrict__ cols,
                const float* __restrict__ vals,
                float* __restrict__ outc,           // fp32, stride OD
                const float* __restrict__ Ws, const float* __restrict__ bs,
                const float* __restrict__ Wp, const float* __restrict__ bp,
                int srcbuf, int ntiles) {
    extern __shared__ char smem[];
    __half* sA    = reinterpret_cast<__half*>(smem + SM_A);
    float*  sF    = reinterpret_cast<float*>(smem + SM_A);   // epilogue bounce
    __half* sW    = reinterpret_cast<__half*>(smem + SM_W);
    float*  sbias = reinterpret_cast<float*>(smem + SM_BIAS);

    const __half* ph  = g_ph[srcbuf];
    __half*       phd = g_ph[srcbuf ^ 1];

    int tx = threadIdx.x;

    // stage weights transposed: sW[n][k] = (k<64 ? Ws[k][n] : Wp[k-64][n])
    for (int idx = tx; idx < 64 * 128; idx += 256) {
        int n = idx >> 7;
        int k = idx & 127;
        float w = (k < 64) ? Ws[k * 64 + n] : Wp[(k - 64) * 64 + n];
        sW[n * SW_STRIDE + k] = __float2half_rn(w);
    }
    if (tx < 64) sbias[tx] = bs[tx] + bp[tx];

    int h  = tx >> 4;          // half-warp id (gather/writeout phases)
    int hl = tx & 15;
    unsigned hmask = 0xFFFFu << (tx & 16);
    int w    = tx >> 5;        // warp id (mma phase)
    int lane = tx & 31;
    int g    = lane >> 2;      // fragment row group
    int t    = lane & 3;       // fragment thread-in-group
    __syncthreads();

    for (int tile = blockIdx.x; tile < ntiles; tile += gridDim.x) {
        int tb = tile * TILE_M;

        // ---- Phase A: gather 8 rows per half-warp (all-fp16 src), stage ----
        #pragma unroll 2
        for (int i = 0; i < 8; i++) {
            int r = h * 8 + i;
            int n = tb + r;
            uint2* dS = reinterpret_cast<uint2*>(sA + r * SA_STRIDE + hl * 4);
            uint2* dP = reinterpret_cast<uint2*>(sA + r * SA_STRIDE + 64 + hl * 4);
            if (n >= N_NODES) {
                *dS = make_uint2(0u, 0u);
                *dP = make_uint2(0u, 0u);
                continue;
            }
            uint2 us = __ldcg(reinterpret_cast<const uint2*>(ph + (size_t)n * D) + hl);
            float2 sa = __half22float2(H2(us.x));
            float2 sb = __half22float2(H2(us.y));
            float4 pself = make_float4(sa.x, sa.y, sb.x, sb.y);
            float4 acc = pself;
            if (n < N_USERS) {
                const int* cu = cols + n * KPU;
                int c_lo = cu[hl];
                int c_hi = cu[16 + hl];
                gather8h(ph, hmask, c_lo, 0, hl, acc);
                gather8h(ph, hmask, c_lo, 8, hl, acc);
                gather8h(ph, hmask, c_hi, 0, hl, acc);
                gather8h(ph, hmask, c_hi, 8, hl, acc);
            } else {
                int it  = n - N_USERS;
                int cnt = g_fill[it]; if (cnt > MAXDEG) cnt = MAXDEG;
                const int* adj = g_adj2 + (size_t)it * MAXDEG;
                int p = 0;
                int myu = (cnt >= 16) ? adj[hl] : 0;   // prefetched chunk
                for (; p + 16 <= cnt; p += 16) {
                    int cur = myu;
                    // prefetch next chunk's indices before consuming current
                    if (p + 32 <= cnt) myu = adj[p + 16 + hl];
                    gather8h(ph, hmask, cur, 0, hl, acc);
                    gather8h(ph, hmask, cur, 8, hl, acc);
                }
                int rem = cnt - p;
                if (rem > 0) {
                    int mr = (hl < rem) ? adj[p + hl] : 0;
                    for (int j = 0; j < rem; j++) {
                        int uu = __shfl_sync(hmask, mr, j, 16);
                        uint2 u = __ldcg(reinterpret_cast<const uint2*>(ph + (size_t)uu * D) + hl);
                        float2 a = __half22float2(H2(u.x));
                        float2 b = __half22float2(H2(u.y));
                        acc.x += a.x; acc.y += a.y; acc.z += b.x; acc.w += b.y;
                    }
                }
            }
            float sv = vals[SELF_BASE + n];   // 1/deg[n]
            float4 sd = make_float4(acc.x*sv, acc.y*sv, acc.z*sv, acc.w*sv);
            float4 pp = make_float4(sd.x*pself.x, sd.y*pself.y, sd.z*pself.z, sd.w*pself.w);
            __half2 s0 = __floats2half2_rn(sd.x, sd.y);
            __half2 s1 = __floats2half2_rn(sd.z, sd.w);
            __half2 p0 = __floats2half2_rn(pp.x, pp.y);
            __half2 p1 = __floats2half2_rn(pp.z, pp.w);
            *dS = make_uint2(*reinterpret_cast<unsigned*>(&s0),
                             *reinterpret_cast<unsigned*>(&s1));
            *dP = make_uint2(*reinterpret_cast<unsigned*>(&p0),
                             *reinterpret_cast<unsigned*>(&p1));
        }
        __syncthreads();

        // ---- Phase B: warp stripe GEMM, rows [16w, 16w+16), via HMMA ----
        float acc[8][4];
        #pragma unroll
        for (int nt = 0; nt < 8; nt++) {
            acc[nt][0] = 0.f; acc[nt][1] = 0.f; acc[nt][2] = 0.f; acc[nt][3] = 0.f;
        }
        #pragma unroll
        for (int ks = 0; ks < 8; ks++) {
            const __half* pa = sA + (w * 16 + g) * SA_STRIDE + ks * 16 + t * 2;
            uint32_t a0 = *reinterpret_cast<const uint32_t*>(pa);
            uint32_t a1 = *reinterpret_cast<const uint32_t*>(pa + 8 * SA_STRIDE);
            uint32_t a2 = *reinterpret_cast<const uint32_t*>(pa + 8);
            uint32_t a3 = *reinterpret_cast<const uint32_t*>(pa + 8 * SA_STRIDE + 8);
            #pragma unroll
            for (int nt = 0; nt < 8; nt++) {
                const __half* pb = sW + (nt * 8 + g) * SW_STRIDE + ks * 16 + t * 2;
                uint32_t b0 = *reinterpret_cast<const uint32_t*>(pb);
                uint32_t b1 = *reinterpret_cast<const uint32_t*>(pb + 8);
                mma16816(acc[nt], a0, a1, a2, a3, b0, b1);
            }
        }

        // ---- epilogue: bias + lrelu + L2 norm, bounce through smem ----
        {
            int lr0 = w * 16 + g;
            int lr1 = lr0 + 8;
            float sq0 = 0.f, sq1 = 0.f;
            #pragma unroll
            for (int nt = 0; nt < 8; nt++) {
                float b0v = sbias[nt * 8 + t * 2];
                float b1v = sbias[nt * 8 + t * 2 + 1];
                float v;
                v = acc[nt][0] + b0v; v = (v >= 0.f) ? v : 0.2f * v; acc[nt][0] = v; sq0 += v * v;
                v = acc[nt][1] + b1v; v = (v >= 0.f) ? v : 0.2f * v; acc[nt][1] = v; sq0 += v * v;
                v = acc[nt][2] + b0v; v = (v >= 0.f) ? v : 0.2f * v; acc[nt][2] = v; sq1 += v * v;
                v = acc[nt][3] + b1v; v = (v >= 0.f) ? v : 0.2f * v; acc[nt][3] = v; sq1 += v * v;
            }
            sq0 += __shfl_xor_sync(0xffffffffu, sq0, 1);
            sq0 += __shfl_xor_sync(0xffffffffu, sq0, 2);
            sq1 += __shfl_xor_sync(0xffffffffu, sq1, 1);
            sq1 += __shfl_xor_sync(0xffffffffu, sq1, 2);
            float inv0 = 1.0f / fmaxf(sqrtf(sq0), 1e-12f);
            float inv1 = 1.0f / fmaxf(sqrtf(sq1), 1e-12f);
            #pragma unroll
            for (int nt = 0; nt < 8; nt++) {
                *reinterpret_cast<float2*>(sF + lr0 * SF_STRIDE + nt * 8 + t * 2) =
                    make_float2(acc[nt][0] * inv0, acc[nt][1] * inv0);
                *reinterpret_cast<float2*>(sF + lr1 * SF_STRIDE + nt * 8 + t * 2) =
                    make_float2(acc[nt][2] * inv1, acc[nt][3] * inv1);
            }
        }
        __syncthreads();

        // ---- coalesced writeout: half-warp h writes rows h*8..h*8+7 ----
        // fp32 out is NEVER re-read by kernels (fp16 ping-pong feeds next layer)
        // -> evict-first streaming store keeps L2 for the gather table.
        #pragma unroll 2
        for (int i = 0; i < 8; i++) {
            int r = h * 8 + i;
            int n = tb + r;
            if (n < N_NODES) {
                float4 v = *reinterpret_cast<const float4*>(sF + r * SF_STRIDE + hl * 4);
                __stcs(reinterpret_cast<float4*>(outc + (size_t)n * OD) + hl, v);
                __half2 h0 = __floats2half2_rn(v.x, v.y);
                __half2 h1 = __floats2half2_rn(v.z, v.w);
                reinterpret_cast<uint2*>(phd + (size_t)n * D)[hl] =
                    make_uint2(*reinterpret_cast<unsigned*>(&h0),
                               *reinterpret_cast<unsigned*>(&h1));
            }
        }
        __syncthreads();   // sF/sA reused next tile
    }
}

// ---------------- launch ----------------
extern "C" void kernel_launch(void* const* d_in, const int* in_sizes, int n_in,
                              void* d_out, int out_size) {
    (void)in_sizes; (void)n_in; (void)out_size;
    const int*   cols = (const int*)d_in[1];
    const float* vals = (const float*)d_in[2];
    const float* ue   = (const float*)d_in[3];
    const float* ie   = (const float*)d_in[4];
    float* out = (float*)d_out;

    static int smem_set = 0;
    if (!smem_set) {
        cudaFuncSetAttribute(fused_layer_mma,
                             cudaFuncAttributeMaxDynamicSharedMemorySize, SM_TOTAL);
        smem_set = 1;
    }

    // (1) zero counters + ego copy + fp16 pack, single launch
    init_kernel<<<(N_NODES * (D/4) + 255) / 256, 256>>>(ue, ie, out);
    // (2) build padded item->user adjacency
    fill2_kernel<<<(E_UI + 255) / 256, 256>>>(cols);

    int nblk = 148 * 4;   // grid-stride, one wave at 4 CTAs/SM
    for (int k = 0; k < 3; k++) {
        float* outc = out + (size_t)64 * (k + 1);
        const float* Ws = (const float*)d_in[5 + 4 * k + 0];
        const float* bs = (const float*)d_in[5 + 4 * k + 1];
        const float* Wp = (const float*)d_in[5 + 4 * k + 2];
        const float* bp = (const float*)d_in[5 + 4 * k + 3];
        fused_layer_mma<<<nblk, 256, SM_TOTAL>>>(cols, vals, outc,
                                                 Ws, bs, Wp, bp, k & 1, NTILES);
    }
}